// round 12
// baseline (speedup 1.0000x reference)
#include <cuda_runtime.h>

#define NZ 32
#define NY 1024
#define NX 1024
#define SX (1.0f / (1000.0f * 6.0f))   // DXI/6 (fluxes carry uniform x6)
#define SY (1.0f / (1000.0f * 6.0f))
#define JSTRIP 64
#define WARPS 4

typedef unsigned long long u64_t;

__device__ __forceinline__ u64_t pk2(float lo, float hi) {
    u64_t r; asm("mov.b64 %0, {%1, %2};" : "=l"(r) : "f"(lo), "f"(hi)); return r;
}
__device__ __forceinline__ void upk2(u64_t p, float& lo, float& hi) {
    asm("mov.b64 {%0, %1}, %2;" : "=f"(lo), "=f"(hi) : "l"(p));
}
__device__ __forceinline__ u64_t f2add(u64_t a, u64_t b) {
    u64_t r; asm("add.rn.f32x2 %0, %1, %2;" : "=l"(r) : "l"(a), "l"(b)); return r;
}
__device__ __forceinline__ u64_t f2mul(u64_t a, u64_t b) {
    u64_t r; asm("mul.rn.f32x2 %0, %1, %2;" : "=l"(r) : "l"(a), "l"(b)); return r;
}
__device__ __forceinline__ u64_t f2fma(u64_t a, u64_t b, u64_t c) {
    u64_t r; asm("fma.rn.f32x2 %0, %1, %2, %3;" : "=l"(r) : "l"(a), "l"(b), "l"(c)); return r;
}
__device__ __forceinline__ u64_t bcast2(float x) {
    unsigned uu = __float_as_uint(x);
    return ((u64_t)uu << 32) | (u64_t)uu;
}

// 8-byte async copy global -> shared (own lane's data only)
__device__ __forceinline__ void cp8(void* sdst, const void* gsrc) {
    unsigned sa = (unsigned)__cvta_generic_to_shared(sdst);
    asm volatile("cp.async.ca.shared.global [%0], [%1], 8;" :: "r"(sa), "l"(gsrc) : "memory");
}
#define CP_COMMIT()  asm volatile("cp.async.commit_group;" ::: "memory")
#define CP_WAIT3()   asm volatile("cp.async.wait_group 3;" ::: "memory")
#define CP_WAITALL() asm volatile("cp.async.wait_all;" ::: "memory")

// Packed WENO5 (Jiang-Shu). Smoothness indicators carry per-stencil scale factors
// (sqrt6 / 1 / sqrt2) so weight ratios 1:6:3 fall out of bare products.
// Candidate polys scaled x6; the 1/6 is folded into SX/SY.
__device__ __forceinline__ void weno5x2(u64_t qm2, u64_t qm1, u64_t q0,
                                        u64_t qp1, u64_t qp2,
                                        float& r0, float& r1) {
    const u64_t cm2 = bcast2(-2.f), cm4 = bcast2(-4.f), c3 = bcast2(3.f),
                cm1 = bcast2(-1.f),
                c2  = bcast2(2.f),  cm7 = bcast2(-7.f), c11 = bcast2(11.f),
                c5  = bcast2(5.f);
    const u64_t c13a = bcast2(31.84337001f), c3a = bcast2(7.34846926f),
                cEa  = bcast2(2.93938761e-5f);
    const u64_t c13b = bcast2(13.f),         c3b = bcast2(3.f),
                cEb  = bcast2(1.2e-5f);
    const u64_t c13c = bcast2(18.38477631f), c3c = bcast2(4.24264069f),
                cEc  = bcast2(1.69705627e-5f);

    u64_t t0 = f2add(f2fma(qm1, cm2, q0), qm2);
    u64_t s0 = f2fma(qm1, cm4, f2fma(q0, c3, qm2));
    u64_t B0 = f2fma(f2mul(t0, c13a), t0, f2mul(f2mul(s0, s0), c3a));
    u64_t t1 = f2add(f2fma(q0, cm2, qp1), qm1);
    u64_t s1 = f2fma(qp1, cm1, qm1);
    u64_t B1 = f2fma(f2mul(t1, c13b), t1, f2mul(f2mul(s1, s1), c3b));
    u64_t t2 = f2add(f2fma(qp1, cm2, qp2), q0);
    u64_t s2 = f2fma(qp1, cm4, f2fma(q0, c3, qp2));
    u64_t B2 = f2fma(f2mul(t2, c13c), t2, f2mul(f2mul(s2, s2), c3c));

    u64_t d0 = f2add(B0, cEa); d0 = f2mul(d0, d0);   // = 6 * d0_std
    u64_t d1 = f2add(B1, cEb); d1 = f2mul(d1, d1);   // =     d1_std
    u64_t d2 = f2add(B2, cEc); d2 = f2mul(d2, d2);   // = 2 * d2_std

    u64_t w0 = f2mul(d1, d2);
    u64_t w1 = f2mul(d0, d2);
    u64_t w2 = f2mul(d0, d1);

    u64_t P0 = f2fma(qm2, c2, f2fma(qm1, cm7, f2mul(q0, c11)));
    u64_t P1 = f2fma(qm1, cm1, f2fma(q0, c5, f2mul(qp1, c2)));
    u64_t P2 = f2fma(q0, c2, f2fma(qp1, c5, f2mul(qp2, cm1)));

    u64_t num = f2fma(w0, P0, f2fma(w1, P1, f2mul(w2, P2)));
    u64_t den = f2add(w0, f2add(w1, w2));
    float n0, n1, e0, e1;
    upk2(num, n0, n1); upk2(den, e0, e1);
    r0 = __fdividef(n0, e0);
    r1 = __fdividef(n1, e1);
}

__device__ __forceinline__ void upwind_pack(const float a[6], const float b[6],
                                            bool ga, bool gb,
                                            u64_t& m2, u64_t& m1, u64_t& z0,
                                            u64_t& p1, u64_t& p2) {
    m2 = pk2(ga ? a[0] : a[5], gb ? b[0] : b[5]);
    m1 = pk2(ga ? a[1] : a[4], gb ? b[1] : b[4]);
    z0 = pk2(ga ? a[2] : a[3], gb ? b[2] : b[3]);
    p1 = pk2(ga ? a[3] : a[2], gb ? b[3] : b[2]);
    p2 = pk2(ga ? a[4] : a[1], gb ? b[4] : b[1]);
}

__device__ __forceinline__ float2 ld2(const float* p) {
    return __ldg((const float2*)p);
}

// MODE: 0 = first strip (js==0, j>=2 mask), 1 = interior, 2 = last strip (clamps + mask).
// Ring discipline: group g (prologue 0..3, loop iter jj -> group jj+4) holds
// {h row js+5+g, u row js+g, v row js+g}. In-loop CP_WAIT3 before LDS guarantees
// groups 0..jj complete => h row j+5, u/v row j are readable (4-group slack).
template<int MODE>
__device__ __forceinline__ void strip_loop(
    const float* __restrict__ h, const float* __restrict__ u,
    const float* __restrict__ v, float* __restrict__ out,
    int base, int ip, int js, int lane, float sxs, float sys,
    bool left_edge, bool right_edge,
    const float* sF, const float* sH8,
    float (*sHr)[64], float (*sUr)[64], float (*sVr)[64],
    float2 r0, float2 r1, float2 r2, float2 r3, float2 r4, float2 r5,
    float2 r6, float2 r7, float2 fn_prev)
{
    const unsigned FULL = 0xffffffffu;
    const int l2 = 2 * lane;
    const float* hsrc = h + base + (js + 9) * NX + ip;
    const float* usrc = u + base + (js + 4) * NX + ip;
    const float* vsrc = v + base + (js + 4) * NX + ip;
    float*       op   = out + base + js * NX + ip;

    #pragma unroll 8
    for (int jj = 0; jj < JSTRIP; jj++) {
        const int j = js + jj;

        // ---- wait for group jj, then read this iteration's ring data ----
        CP_WAIT3();
        float2 r7n = *(const float2*)&sHr[(jj + 5) & 7][l2];   // h row j+5
        float2 uv  = *(const float2*)&sUr[jj & 7][l2];         // u row j
        float2 vv  = *(const float2*)&sVr[jj & 7][l2];         // v row j

        // ---- issue next group: h row j+9, u/v row j+4 ----
        if (MODE == 2) {
            int hr = min(j + 9, NY - 1), ur = min(j + 4, NY - 1);
            cp8(&sHr[(jj + 1) & 7][l2], &h[base + hr * NX + ip]);
            cp8(&sUr[(jj + 4) & 7][l2], &u[base + ur * NX + ip]);
            cp8(&sVr[(jj + 4) & 7][l2], &v[base + ur * NX + ip]);
        } else {
            cp8(&sHr[(jj + 1) & 7][l2], hsrc);
            cp8(&sUr[(jj + 4) & 7][l2], usrc);
            cp8(&sVr[(jj + 4) & 7][l2], vsrc);
            hsrc += NX; usrc += NX; vsrc += NX;
        }
        CP_COMMIT();

        // ---- shift rows: r0..r7 = rows j-2..j+5 ----
        r0 = r1; r1 = r2; r2 = r3; r3 = r4; r4 = r5; r5 = r6; r6 = r7; r7 = r7n;
        float2 c = r2;                               // center row j

        // x-stencil neighbors via intra-warp shuffle
        float2 L, R1, R2;
        L.x  = __shfl_up_sync(FULL, c.x, 1);
        L.y  = __shfl_up_sync(FULL, c.y, 1);
        R1.x = __shfl_down_sync(FULL, c.x, 1);
        R1.y = __shfl_down_sync(FULL, c.y, 1);
        R2.x = __shfl_down_sync(FULL, c.x, 2);
        R2.y = __shfl_down_sync(FULL, c.y, 2);

        // edge / cross-warp fixups from smem halo (lanes 0, 30, 31 only)
        const float* hrow = &sH8[jj * 8];
        if (lane == 0)
            L = left_edge ? make_float2(c.x, c.x) : *(const float2*)&hrow[2];
        if (lane == 31) {
            R1 = right_edge ? make_float2(c.y, c.y) : *(const float2*)&hrow[4];
            R2 = right_edge ? make_float2(c.y, c.y) : *(const float2*)&hrow[6];
        } else if (lane == 30) {
            R2 = right_edge ? make_float2(R1.y, R1.y) : *(const float2*)&hrow[4];
        }

        // ---- x faces at (ip, ip+1) ----
        float fx0, fx1;
        {
            float ax[6] = {L.x, L.y, c.x, c.y, R1.x, R1.y};
            float bx[6] = {L.y, c.x, c.y, R1.x, R1.y, R2.x};
            u64_t m2, m1, z0, p1, p2;
            upwind_pack(ax, bx, uv.x >= 0.f, uv.y >= 0.f, m2, m1, z0, p1, p2);
            weno5x2(m2, m1, z0, p1, p2, fx0, fx1);
            fx0 *= uv.x; fx1 *= uv.y;
        }
        float fxm = __shfl_up_sync(FULL, fx1, 1);    // face at ip-1 from left lane
        float halo = sF[jj];
        if (lane == 0) fxm = halo;

        // ---- y faces at row j (rows j-2..j+3 = r0..r5) ----
        float fy0, fy1;
        {
            float ay[6] = {r0.x, r1.x, r2.x, r3.x, r4.x, r5.x};
            float by[6] = {r0.y, r1.y, r2.y, r3.y, r4.y, r5.y};
            u64_t m2, m1, z0, p1, p2;
            upwind_pack(ay, by, vv.x >= 0.f, vv.y >= 0.f, m2, m1, z0, p1, p2);
            weno5x2(m2, m1, z0, p1, p2, fy0, fy1);
            fy0 *= vv.x; fy1 *= vv.y;
        }

        // ---- divergence via pre-masked multipliers (sxs/sys carry -1 and xok) ----
        float sx = sxs, sy = sys;
        if (MODE == 0) { bool jok = (j >= 2);      sx = jok ? sxs : 0.f; sy = jok ? sys : 0.f; }
        if (MODE == 2) { bool jok = (j <= NY - 3); sx = jok ? sxs : 0.f; sy = jok ? sys : 0.f; }
        float o0 = (fx0 - fxm ) * sx + (fy0 - fn_prev.x) * sy;
        float o1 = (fx1 - fx0) * sx + (fy1 - fn_prev.y) * sy;
        __stcs((float2*)op, make_float2(o0, o1));

        fn_prev = make_float2(fy0, fy1);
        op += NX;
    }
    CP_WAITALL();   // no outstanding async copies at exit
}

__global__ __launch_bounds__(32 * WARPS, 6)
void adv3d_kernel(const float* __restrict__ h,
                  const float* __restrict__ u,
                  const float* __restrict__ v,
                  float* __restrict__ out) {
    const int k    = blockIdx.z;
    const int lane = threadIdx.x;
    const int w    = threadIdx.y;
    const int i0   = (blockIdx.x * WARPS + w) * 64;
    const int ip   = i0 + 2 * lane;
    const int js   = blockIdx.y * JSTRIP;
    const int base = k * (NY * NX);

    if (k == 0 || k == NZ - 1) {                 // z boundary slabs: zeros
        float* op = out + base + js * NX + ip;
        #pragma unroll 4
        for (int jj = 0; jj < JSTRIP; jj++) {
            __stcs((float2*)op, make_float2(0.f, 0.f));
            op += NX;
        }
        return;
    }

    __shared__ __align__(16) float sHring[WARPS][8][64];   // h rows ring
    __shared__ __align__(16) float sUring[WARPS][8][64];   // u rows ring
    __shared__ __align__(16) float sVring[WARPS][8][64];   // v rows ring
    __shared__ float sHaloF[WARPS][JSTRIP];                // x-halo FLUX at i0-1 per row
    __shared__ __align__(16) float sHaloH[WARPS][JSTRIP][8]; // h halo cols per row

    const int l2 = 2 * lane;

    // ---- prime the rings: 4 groups {h row js+5+i, u row js+i, v row js+i} ----
    // (rows js+5..js+8 and js..js+3 are always in-bounds: js <= 960)
    #pragma unroll
    for (int i = 0; i < 4; i++) {
        cp8(&sHring[w][(5 + i) & 7][l2], &h[base + (js + 5 + i) * NX + ip]);
        cp8(&sUring[w][i & 7][l2],       &u[base + (js + i) * NX + ip]);
        cp8(&sVring[w][i & 7][l2],       &v[base + (js + i) * NX + ip]);
        CP_COMMIT();
    }

    const bool left_edge  = (i0 == 0);
    const bool right_edge = (i0 == NX - 64);
    const bool xok = !((left_edge && lane == 0) || (right_edge && lane == 31));
    const float sxs = xok ? -SX : 0.f;
    const float sys = xok ? -SY : 0.f;

    // ---- pre-phase A: stage halo h-columns for all 64 rows into smem ----
    {
        const int lcol = max(i0 - 4, 0);
        const int rcol = min(i0 + 64, NX - 4);
        #pragma unroll
        for (int m = 0; m < 2; m++) {
            int rr = 2 * lane + m;
            int row = js + rr;
            float4 lq = __ldg((const float4*)&h[base + row * NX + lcol]);
            float4 rq = __ldg((const float4*)&h[base + row * NX + rcol]);
            *(float4*)&sHaloH[w][rr][0] = lq;
            *(float4*)&sHaloH[w][rr][4] = rq;
        }
    }

    // ---- pre-phase B: x-halo faces at x = i0-1 for all 64 rows (one packed eval/lane) ----
    {
        int ra = js + 2 * lane, rb = ra + 1;
        float a[6], b[6];
        #pragma unroll
        for (int m = 0; m < 6; m++) {
            int xi = min(max(i0 - 3 + m, 0), NX - 1);
            a[m] = __ldg(&h[base + ra * NX + xi]);
            b[m] = __ldg(&h[base + rb * NX + xi]);
        }
        int xh = max(i0 - 1, 0);
        float ua = __ldg(&u[base + ra * NX + xh]);
        float ub = __ldg(&u[base + rb * NX + xh]);
        u64_t m2, m1, z0, p1, p2;
        upwind_pack(a, b, ua >= 0.f, ub >= 0.f, m2, m1, z0, p1, p2);
        float f0, f1;
        weno5x2(m2, m1, z0, p1, p2, f0, f1);
        sHaloF[w][2 * lane]     = f0 * ua;
        sHaloF[w][2 * lane + 1] = f1 * ub;
    }
    __syncwarp();

    // ---- warm-up registers: r0..r7 = rows js-3..js+4 (clamped low) ----
    float2 r0, r1, r2, r3, r4, r5, r6, r7;
    {
        #define LOADROW(m) ld2(&h[base + min(max(js - 3 + (m), 0), NY - 1) * NX + ip])
        r0 = LOADROW(0); r1 = LOADROW(1); r2 = LOADROW(2); r3 = LOADROW(3);
        r4 = LOADROW(4); r5 = LOADROW(5); r6 = LOADROW(6); r7 = LOADROW(7);
        #undef LOADROW
    }

    // fn_prev: y-face at row js-1 (stencil rows js-3..js+2 = r0..r5)
    float2 fn_prev;
    {
        float2 vh = ld2(&v[base + max(js - 1, 0) * NX + ip]);
        float ay[6] = {r0.x, r1.x, r2.x, r3.x, r4.x, r5.x};
        float by[6] = {r0.y, r1.y, r2.y, r3.y, r4.y, r5.y};
        u64_t m2, m1, z0, p1, p2;
        upwind_pack(ay, by, vh.x >= 0.f, vh.y >= 0.f, m2, m1, z0, p1, p2);
        float f0, f1;
        weno5x2(m2, m1, z0, p1, p2, f0, f1);
        fn_prev = make_float2(f0 * vh.x, f1 * vh.y);
    }

    if (js == 0)
        strip_loop<0>(h, u, v, out, base, ip, js, lane, sxs, sys, left_edge, right_edge,
                      &sHaloF[w][0], &sHaloH[w][0][0],
                      sHring[w], sUring[w], sVring[w],
                      r0, r1, r2, r3, r4, r5, r6, r7, fn_prev);
    else if (js == NY - JSTRIP)
        strip_loop<2>(h, u, v, out, base, ip, js, lane, sxs, sys, left_edge, right_edge,
                      &sHaloF[w][0], &sHaloH[w][0][0],
                      sHring[w], sUring[w], sVring[w],
                      r0, r1, r2, r3, r4, r5, r6, r7, fn_prev);
    else
        strip_loop<1>(h, u, v, out, base, ip, js, lane, sxs, sys, left_edge, right_edge,
                      &sHaloF[w][0], &sHaloH[w][0][0],
                      sHring[w], sUring[w], sVring[w],
                      r0, r1, r2, r3, r4, r5, r6, r7, fn_prev);
}

extern "C" void kernel_launch(void* const* d_in, const int* in_sizes, int n_in,
                              void* d_out, int out_size) {
    const float* h = (const float*)d_in[0];
    const float* u = (const float*)d_in[1];
    const float* v = (const float*)d_in[2];
    float* out = (float*)d_out;

    dim3 block(32, WARPS, 1);
    dim3 grid(NX / (64 * WARPS), NY / JSTRIP, NZ);
    adv3d_kernel<<<grid, block>>>(h, u, v, out);
}

// round 14
// speedup vs baseline: 1.1264x; 1.1264x over previous
#include <cuda_runtime.h>

#define NZ 32
#define NY 1024
#define NX 1024
#define SX (1.0f / (1000.0f * 6.0f))   // DXI/6 (fluxes carry uniform x6)
#define SY (1.0f / (1000.0f * 6.0f))
#define JSTRIP 64
#define WARPS 4

typedef unsigned long long u64_t;

__device__ __forceinline__ u64_t pk2(float lo, float hi) {
    u64_t r; asm("mov.b64 %0, {%1, %2};" : "=l"(r) : "f"(lo), "f"(hi)); return r;
}
__device__ __forceinline__ void upk2(u64_t p, float& lo, float& hi) {
    asm("mov.b64 {%0, %1}, %2;" : "=f"(lo), "=f"(hi) : "l"(p));
}
__device__ __forceinline__ u64_t f2add(u64_t a, u64_t b) {
    u64_t r; asm("add.rn.f32x2 %0, %1, %2;" : "=l"(r) : "l"(a), "l"(b)); return r;
}
__device__ __forceinline__ u64_t f2mul(u64_t a, u64_t b) {
    u64_t r; asm("mul.rn.f32x2 %0, %1, %2;" : "=l"(r) : "l"(a), "l"(b)); return r;
}
__device__ __forceinline__ u64_t f2fma(u64_t a, u64_t b, u64_t c) {
    u64_t r; asm("fma.rn.f32x2 %0, %1, %2, %3;" : "=l"(r) : "l"(a), "l"(b), "l"(c)); return r;
}
__device__ __forceinline__ u64_t bcast2(float x) {
    unsigned uu = __float_as_uint(x);
    return ((u64_t)uu << 32) | (u64_t)uu;
}

// Packed WENO5 (Jiang-Shu). Smoothness indicators carry per-stencil scale factors
// (sqrt6 / 1 / sqrt2) so weight ratios 1:6:3 fall out of bare products.
// Candidate polys scaled x6; the 1/6 is folded into SX/SY.
__device__ __forceinline__ void weno5x2(u64_t qm2, u64_t qm1, u64_t q0,
                                        u64_t qp1, u64_t qp2,
                                        float& r0, float& r1) {
    const u64_t cm2 = bcast2(-2.f), cm4 = bcast2(-4.f), c3 = bcast2(3.f),
                cm1 = bcast2(-1.f),
                c2  = bcast2(2.f),  cm7 = bcast2(-7.f), c11 = bcast2(11.f),
                c5  = bcast2(5.f);
    const u64_t c13a = bcast2(31.84337001f), c3a = bcast2(7.34846926f),
                cEa  = bcast2(2.93938761e-5f);
    const u64_t c13b = bcast2(13.f),         c3b = bcast2(3.f),
                cEb  = bcast2(1.2e-5f);
    const u64_t c13c = bcast2(18.38477631f), c3c = bcast2(4.24264069f),
                cEc  = bcast2(1.69705627e-5f);

    u64_t t0 = f2add(f2fma(qm1, cm2, q0), qm2);
    u64_t s0 = f2fma(qm1, cm4, f2fma(q0, c3, qm2));
    u64_t B0 = f2fma(f2mul(t0, c13a), t0, f2mul(f2mul(s0, s0), c3a));
    u64_t t1 = f2add(f2fma(q0, cm2, qp1), qm1);
    u64_t s1 = f2fma(qp1, cm1, qm1);
    u64_t B1 = f2fma(f2mul(t1, c13b), t1, f2mul(f2mul(s1, s1), c3b));
    u64_t t2 = f2add(f2fma(qp1, cm2, qp2), q0);
    u64_t s2 = f2fma(qp1, cm4, f2fma(q0, c3, qp2));
    u64_t B2 = f2fma(f2mul(t2, c13c), t2, f2mul(f2mul(s2, s2), c3c));

    u64_t d0 = f2add(B0, cEa); d0 = f2mul(d0, d0);   // = 6 * d0_std
    u64_t d1 = f2add(B1, cEb); d1 = f2mul(d1, d1);   // =     d1_std
    u64_t d2 = f2add(B2, cEc); d2 = f2mul(d2, d2);   // = 2 * d2_std

    u64_t w0 = f2mul(d1, d2);
    u64_t w1 = f2mul(d0, d2);
    u64_t w2 = f2mul(d0, d1);

    u64_t P0 = f2fma(qm2, c2, f2fma(qm1, cm7, f2mul(q0, c11)));
    u64_t P1 = f2fma(qm1, cm1, f2fma(q0, c5, f2mul(qp1, c2)));
    u64_t P2 = f2fma(q0, c2, f2fma(qp1, c5, f2mul(qp2, cm1)));

    u64_t num = f2fma(w0, P0, f2fma(w1, P1, f2mul(w2, P2)));
    u64_t den = f2add(w0, f2add(w1, w2));
    float n0, n1, e0, e1;
    upk2(num, n0, n1); upk2(den, e0, e1);
    r0 = __fdividef(n0, e0);
    r1 = __fdividef(n1, e1);
}

__device__ __forceinline__ void upwind_pack(const float a[6], const float b[6],
                                            bool ga, bool gb,
                                            u64_t& m2, u64_t& m1, u64_t& z0,
                                            u64_t& p1, u64_t& p2) {
    m2 = pk2(ga ? a[0] : a[5], gb ? b[0] : b[5]);
    m1 = pk2(ga ? a[1] : a[4], gb ? b[1] : b[4]);
    z0 = pk2(ga ? a[2] : a[3], gb ? b[2] : b[3]);
    p1 = pk2(ga ? a[3] : a[2], gb ? b[3] : b[2]);
    p2 = pk2(ga ? a[4] : a[1], gb ? b[4] : b[1]);
}

__device__ __forceinline__ float2 ld2(const float* p) {
    return __ldg((const float2*)p);
}

#define RINGW 72   // 64 data cols + 8 pad (lane31 overreads stay in-slot)

// MODE: 0 = first strip (js==0, j>=2 mask), 1 = interior, 2 = last strip (clamps + mask).
// Ring invariant at iteration jj (row j = js+jj, js%8==0 so slot(row)=row&7=jj&7):
//   ring holds rows j-2..j+5; this iter reads rows j-2..j+3, writes row j+5
//   (slot (jj+5)&7, disjoint from all read slots). Row written at iter t is
//   first read at iter t+2 -> two __syncwarp()s in between.
template<int MODE>
__device__ __forceinline__ void strip_loop(
    const float* __restrict__ h, const float* __restrict__ u,
    const float* __restrict__ v, float* __restrict__ out,
    int base, int ip, int js, int lane, float sxs, float sys,
    bool left_edge, bool right_edge,
    const float* sF, const float* sH8, float (*sR)[RINGW],
    float2 rfill0, float2 rfill1,
    float2 uv, float2 uv1, float2 vv, float2 vv1, float2 fn_prev)
{
    const unsigned FULL = 0xffffffffu;
    const int l2 = 2 * lane;
    const int xoffc = (l2 >= 2) ? (l2 - 2) : 0;  // clamped left-read offset (lane0 fixed up)
    const float* hsrc = h + base + (js + 7) * NX + ip;
    const float* usrc = u + base + (js + 2) * NX + ip;
    const float* vsrc = v + base + (js + 2) * NX + ip;
    float*       op   = out + base + js * NX + ip;

    #pragma unroll 8
    for (int jj = 0; jj < JSTRIP; jj++) {
        const int j = js + jj;
        const int s = jj & 7;        // compile-time constant per unrolled body

        // ---- global prefetches: h row j+7, u/v row j+2 ----
        float2 hN, uvN, vvN;
        if (MODE == 2) {
            hN  = ld2(&h[base + min(j + 7, NY - 1) * NX + ip]);
            int jn = min(j + 2, NY - 1);
            uvN = ld2(&u[base + jn * NX + ip]);
            vvN = ld2(&v[base + jn * NX + ip]);
        } else {
            hN = ld2(hsrc); uvN = ld2(usrc); vvN = ld2(vsrc);
            hsrc += NX; usrc += NX; vsrc += NX;
        }

        // ---- order prior iterations' STS before this iteration's LDS ----
        __syncwarp();

        // ---- x-stencil row j from ring (cols l2-2 .. l2+5) ----
        float2 Lv = *(const float2*)&sR[s][xoffc];
        float2 c  = *(const float2*)&sR[s][l2];
        float2 R1 = *(const float2*)&sR[s][l2 + 2];
        float2 R2 = *(const float2*)&sR[s][l2 + 4];

        // ---- y-stencil rows j-2..j+3 at own cols (row j shared with c) ----
        float2 ym2 = *(const float2*)&sR[(s + 6) & 7][l2];
        float2 ym1 = *(const float2*)&sR[(s + 7) & 7][l2];
        float2 yp1 = *(const float2*)&sR[(s + 1) & 7][l2];
        float2 yp2 = *(const float2*)&sR[(s + 2) & 7][l2];
        float2 yp3 = *(const float2*)&sR[(s + 3) & 7][l2];

        // ---- ring fill: store row j+5 (loaded 2 iters ago), rotate relay ----
        *(float2*)&sR[(s + 5) & 7][l2] = rfill0;
        rfill0 = rfill1; rfill1 = hN;

        // ---- edge / cross-warp fixups from halo smem (lanes 0, 30, 31 only) ----
        const float* hrow = &sH8[jj * 8];
        if (lane == 0)
            Lv = left_edge ? make_float2(c.x, c.x) : *(const float2*)&hrow[2];
        if (lane == 31) {
            R1 = right_edge ? make_float2(c.y, c.y) : *(const float2*)&hrow[4];
            R2 = right_edge ? make_float2(c.y, c.y) : *(const float2*)&hrow[6];
        } else if (lane == 30) {
            R2 = right_edge ? make_float2(R1.y, R1.y) : *(const float2*)&hrow[4];
        }

        // ---- x faces at (ip, ip+1) ----
        float fx0, fx1;
        {
            float ax[6] = {Lv.x, Lv.y, c.x, c.y, R1.x, R1.y};
            float bx[6] = {Lv.y, c.x, c.y, R1.x, R1.y, R2.x};
            u64_t m2, m1, z0, p1, p2;
            upwind_pack(ax, bx, uv.x >= 0.f, uv.y >= 0.f, m2, m1, z0, p1, p2);
            weno5x2(m2, m1, z0, p1, p2, fx0, fx1);
            fx0 *= uv.x; fx1 *= uv.y;
        }
        float fxm = __shfl_up_sync(FULL, fx1, 1);    // face at ip-1 from left lane
        float halo = sF[jj];
        if (lane == 0) fxm = halo;

        // ---- y faces at row j ----
        float fy0, fy1;
        {
            float ay[6] = {ym2.x, ym1.x, c.x, yp1.x, yp2.x, yp3.x};
            float by[6] = {ym2.y, ym1.y, c.y, yp1.y, yp2.y, yp3.y};
            u64_t m2, m1, z0, p1, p2;
            upwind_pack(ay, by, vv.x >= 0.f, vv.y >= 0.f, m2, m1, z0, p1, p2);
            weno5x2(m2, m1, z0, p1, p2, fy0, fy1);
            fy0 *= vv.x; fy1 *= vv.y;
        }

        // ---- divergence via pre-masked multipliers (sxs/sys carry -1 and xok) ----
        float sx = sxs, sy = sys;
        if (MODE == 0) { bool jok = (j >= 2);      sx = jok ? sxs : 0.f; sy = jok ? sys : 0.f; }
        if (MODE == 2) { bool jok = (j <= NY - 3); sx = jok ? sxs : 0.f; sy = jok ? sys : 0.f; }
        float o0 = (fx0 - fxm ) * sx + (fy0 - fn_prev.x) * sy;
        float o1 = (fx1 - fx0) * sx + (fy1 - fn_prev.y) * sy;
        __stcs((float2*)op, make_float2(o0, o1));

        // ---- rotate pipelines ----
        fn_prev = make_float2(fy0, fy1);
        uv = uv1; uv1 = uvN;
        vv = vv1; vv1 = vvN;
        op += NX;
    }
}

__global__ __launch_bounds__(32 * WARPS, 8)
void adv3d_kernel(const float* __restrict__ h,
                  const float* __restrict__ u,
                  const float* __restrict__ v,
                  float* __restrict__ out) {
    const int k    = blockIdx.z;
    const int lane = threadIdx.x;
    const int w    = threadIdx.y;
    const int i0   = (blockIdx.x * WARPS + w) * 64;
    const int ip   = i0 + 2 * lane;
    const int js   = blockIdx.y * JSTRIP;
    const int base = k * (NY * NX);
    const int l2   = 2 * lane;

    if (k == 0 || k == NZ - 1) {                 // z boundary slabs: zeros
        float* op = out + base + js * NX + ip;
        #pragma unroll 4
        for (int jj = 0; jj < JSTRIP; jj++) {
            __stcs((float2*)op, make_float2(0.f, 0.f));
            op += NX;
        }
        return;
    }

    __shared__ __align__(16) float sRing[WARPS][8][RINGW];   // h row ring
    __shared__ float sHaloF[WARPS][JSTRIP];                  // x-halo FLUX at i0-1 per row
    __shared__ __align__(16) float sHaloH[WARPS][JSTRIP][8]; // h halo cols per row

    const bool left_edge  = (i0 == 0);
    const bool right_edge = (i0 == NX - 64);
    const bool xok = !((left_edge && lane == 0) || (right_edge && lane == 31));
    const float sxs = xok ? -SX : 0.f;
    const float sys = xok ? -SY : 0.f;

    // ---- pre-phase A: stage halo h-columns for all 64 rows into smem ----
    {
        const int lcol = max(i0 - 4, 0);
        const int rcol = min(i0 + 64, NX - 4);
        #pragma unroll
        for (int m = 0; m < 2; m++) {
            int rr = 2 * lane + m;
            int row = js + rr;
            float4 lq = __ldg((const float4*)&h[base + row * NX + lcol]);
            float4 rq = __ldg((const float4*)&h[base + row * NX + rcol]);
            *(float4*)&sHaloH[w][rr][0] = lq;
            *(float4*)&sHaloH[w][rr][4] = rq;
        }
    }

    // ---- pre-phase B: x-halo faces at x = i0-1 for all 64 rows (one packed eval/lane) ----
    {
        int ra = js + 2 * lane, rb = ra + 1;
        float a[6], b[6];
        #pragma unroll
        for (int m = 0; m < 6; m++) {
            int xi = min(max(i0 - 3 + m, 0), NX - 1);
            a[m] = __ldg(&h[base + ra * NX + xi]);
            b[m] = __ldg(&h[base + rb * NX + xi]);
        }
        int xh = max(i0 - 1, 0);
        float ua = __ldg(&u[base + ra * NX + xh]);
        float ub = __ldg(&u[base + rb * NX + xh]);
        u64_t m2, m1, z0, p1, p2;
        upwind_pack(a, b, ua >= 0.f, ub >= 0.f, m2, m1, z0, p1, p2);
        float f0, f1;
        weno5x2(m2, m1, z0, p1, p2, f0, f1);
        sHaloF[w][2 * lane]     = f0 * ua;
        sHaloF[w][2 * lane + 1] = f1 * ub;
    }

    // ---- prime the ring: rows js-2 .. js+4 (7 rows, slot = row & 7; js%8 == 0) ----
    #pragma unroll
    for (int r = 0; r < 7; r++) {
        int row = max(js - 2 + r, 0);            // low clamp (first strip)
        *(float2*)&sRing[w][(r + 6) & 7][l2] = ld2(&h[base + row * NX + ip]);
    }
    // fill relay: rfill0 = row js+5, rfill1 = row js+6 (always in-bounds: js <= 960)
    float2 rfill0 = ld2(&h[base + (js + 5) * NX + ip]);
    float2 rfill1 = ld2(&h[base + (js + 6) * NX + ip]);

    // u/v depth-2 pipeline: uv = row js, uv1 = row js+1
    float2 uv  = ld2(&u[base + js * NX + ip]);
    float2 vv  = ld2(&v[base + js * NX + ip]);
    float2 uv1 = ld2(&u[base + min(js + 1, NY - 1) * NX + ip]);
    float2 vv1 = ld2(&v[base + min(js + 1, NY - 1) * NX + ip]);

    // fn_prev: y-face at row js-1 (stencil rows js-3..js+2, direct loads)
    float2 fn_prev;
    {
        #define LOADROW(m) ld2(&h[base + min(max(js - 3 + (m), 0), NY - 1) * NX + ip])
        float2 q0 = LOADROW(0), q1 = LOADROW(1), q2 = LOADROW(2),
               q3 = LOADROW(3), q4 = LOADROW(4), q5 = LOADROW(5);
        #undef LOADROW
        float2 vh = ld2(&v[base + max(js - 1, 0) * NX + ip]);
        float ay[6] = {q0.x, q1.x, q2.x, q3.x, q4.x, q5.x};
        float by[6] = {q0.y, q1.y, q2.y, q3.y, q4.y, q5.y};
        u64_t m2, m1, z0, p1, p2;
        upwind_pack(ay, by, vh.x >= 0.f, vh.y >= 0.f, m2, m1, z0, p1, p2);
        float f0, f1;
        weno5x2(m2, m1, z0, p1, p2, f0, f1);
        fn_prev = make_float2(f0 * vh.x, f1 * vh.y);
    }

    if (js == 0)
        strip_loop<0>(h, u, v, out, base, ip, js, lane, sxs, sys, left_edge, right_edge,
                      &sHaloF[w][0], &sHaloH[w][0][0], sRing[w],
                      rfill0, rfill1, uv, uv1, vv, vv1, fn_prev);
    else if (js == NY - JSTRIP)
        strip_loop<2>(h, u, v, out, base, ip, js, lane, sxs, sys, left_edge, right_edge,
                      &sHaloF[w][0], &sHaloH[w][0][0], sRing[w],
                      rfill0, rfill1, uv, uv1, vv, vv1, fn_prev);
    else
        strip_loop<1>(h, u, v, out, base, ip, js, lane, sxs, sys, left_edge, right_edge,
                      &sHaloF[w][0], &sHaloH[w][0][0], sRing[w],
                      rfill0, rfill1, uv, uv1, vv, vv1, fn_prev);
}

extern "C" void kernel_launch(void* const* d_in, const int* in_sizes, int n_in,
                              void* d_out, int out_size) {
    const float* h = (const float*)d_in[0];
    const float* u = (const float*)d_in[1];
    const float* v = (const float*)d_in[2];
    float* out = (float*)d_out;

    dim3 block(32, WARPS, 1);
    dim3 grid(NX / (64 * WARPS), NY / JSTRIP, NZ);
    adv3d_kernel<<<grid, block>>>(h, u, v, out);
}

// round 15
// speedup vs baseline: 1.3214x; 1.1732x over previous
#include <cuda_runtime.h>

#define NZ 32
#define NY 1024
#define NX 1024
#define SX (1.0f / (1000.0f * 6.0f))   // DXI/6 (fluxes carry uniform x6)
#define SY (1.0f / (1000.0f * 6.0f))
#define JSTRIP 64
#define WARPS 4

typedef unsigned long long u64_t;

__device__ __forceinline__ u64_t pk2(float lo, float hi) {
    u64_t r; asm("mov.b64 %0, {%1, %2};" : "=l"(r) : "f"(lo), "f"(hi)); return r;
}
__device__ __forceinline__ void upk2(u64_t p, float& lo, float& hi) {
    asm("mov.b64 {%0, %1}, %2;" : "=f"(lo), "=f"(hi) : "l"(p));
}
__device__ __forceinline__ u64_t f2add(u64_t a, u64_t b) {
    u64_t r; asm("add.rn.f32x2 %0, %1, %2;" : "=l"(r) : "l"(a), "l"(b)); return r;
}
__device__ __forceinline__ u64_t f2mul(u64_t a, u64_t b) {
    u64_t r; asm("mul.rn.f32x2 %0, %1, %2;" : "=l"(r) : "l"(a), "l"(b)); return r;
}
__device__ __forceinline__ u64_t f2fma(u64_t a, u64_t b, u64_t c) {
    u64_t r; asm("fma.rn.f32x2 %0, %1, %2, %3;" : "=l"(r) : "l"(a), "l"(b), "l"(c)); return r;
}
__device__ __forceinline__ u64_t bcast2(float x) {
    unsigned uu = __float_as_uint(x);
    return ((u64_t)uu << 32) | (u64_t)uu;
}

// Packed WENO5 (Jiang-Shu), compressed form.
// Smoothness indicators carry per-stencil scale factors (sqrt6 / 1 / sqrt2) so the
// weight ratios 1:6:3 fall out of bare products d1*d2 : d0*d2 : d0*d1.
// Candidate-poly identity: P0 = P1 + 2(t0-t1), P2 = P1 + (t1-t2)   (all x6-scaled),
// hence recon*6 = P1 + (2*w0*(t0-t1) + w2*(t1-t2)) / (w0+w1+w2).
// The 1/6 is folded into SX/SY.
__device__ __forceinline__ void weno5x2(u64_t qm2, u64_t qm1, u64_t q0,
                                        u64_t qp1, u64_t qp2,
                                        float& r0, float& r1) {
    const u64_t cm2 = bcast2(-2.f), cm4 = bcast2(-4.f), c3 = bcast2(3.f),
                cm1 = bcast2(-1.f), c2 = bcast2(2.f), c5 = bcast2(5.f);
    const u64_t c13a = bcast2(31.84337001f), c3a = bcast2(7.34846926f),
                cEa  = bcast2(2.93938761e-5f);
    const u64_t c13b = bcast2(13.f),         c3b = bcast2(3.f),
                cEb  = bcast2(1.2e-5f);
    const u64_t c13c = bcast2(18.38477631f), c3c = bcast2(4.24264069f),
                cEc  = bcast2(1.69705627e-5f);

    u64_t t0 = f2add(f2fma(qm1, cm2, q0), qm2);
    u64_t s0 = f2fma(qm1, cm4, f2fma(q0, c3, qm2));
    u64_t B0 = f2fma(f2mul(t0, c13a), t0, f2mul(f2mul(s0, s0), c3a));
    u64_t t1 = f2add(f2fma(q0, cm2, qp1), qm1);
    u64_t s1 = f2fma(qp1, cm1, qm1);
    u64_t B1 = f2fma(f2mul(t1, c13b), t1, f2mul(f2mul(s1, s1), c3b));
    u64_t t2 = f2add(f2fma(qp1, cm2, qp2), q0);
    u64_t s2 = f2fma(qp1, cm4, f2fma(q0, c3, qp2));
    u64_t B2 = f2fma(f2mul(t2, c13c), t2, f2mul(f2mul(s2, s2), c3c));

    u64_t d0 = f2add(B0, cEa); d0 = f2mul(d0, d0);   // = 6 * d0_std
    u64_t d1 = f2add(B1, cEb); d1 = f2mul(d1, d1);   // =     d1_std
    u64_t d2 = f2add(B2, cEc); d2 = f2mul(d2, d2);   // = 2 * d2_std

    u64_t w0  = f2mul(d1, d2);                       // ratio 1
    u64_t w2  = f2mul(d0, d1);                       // ratio 3
    u64_t den = f2fma(d0, d2, f2add(w0, w2));        // + ratio 6 == w0+w1+w2

    u64_t P1  = f2fma(qm1, cm1, f2fma(q0, c5, f2mul(qp1, c2)));  // x6 candidate
    u64_t d01 = f2fma(t1, cm1, t0);                  // t0 - t1
    u64_t d12 = f2fma(t2, cm1, t1);                  // t1 - t2
    u64_t nump = f2fma(w2, d12, f2mul(w0, f2add(d01, d01)));

    float n0, n1, e0, e1, p0, p1f;
    upk2(nump, n0, n1); upk2(den, e0, e1); upk2(P1, p0, p1f);
    r0 = p0  + __fdividef(n0, e0);
    r1 = p1f + __fdividef(n1, e1);
}

__device__ __forceinline__ void upwind_pack(const float a[6], const float b[6],
                                            bool ga, bool gb,
                                            u64_t& m2, u64_t& m1, u64_t& z0,
                                            u64_t& p1, u64_t& p2) {
    m2 = pk2(ga ? a[0] : a[5], gb ? b[0] : b[5]);
    m1 = pk2(ga ? a[1] : a[4], gb ? b[1] : b[4]);
    z0 = pk2(ga ? a[2] : a[3], gb ? b[2] : b[3]);
    p1 = pk2(ga ? a[3] : a[2], gb ? b[3] : b[2]);
    p2 = pk2(ga ? a[4] : a[1], gb ? b[4] : b[1]);
}

__device__ __forceinline__ float2 ld2(const float* p) {
    return __ldg((const float2*)p);
}

// MODE: 0 = first strip (js==0, j>=2 mask), 1 = interior, 2 = last strip
// (needs row clamps + j<=NY-3 mask).
template<int MODE>
__device__ __forceinline__ void strip_loop(
    const float* __restrict__ h, const float* __restrict__ u,
    const float* __restrict__ v, float* __restrict__ out,
    int base, int ip, int js, int lane, float sxs, float sys,
    bool left_edge, bool right_edge,
    const float* sF, const float* sH8,
    float2 r0, float2 r1, float2 r2, float2 r3, float2 r4, float2 r5,
    float2 rp, float2 rp2, float2 uv, float2 uv1, float2 vv, float2 vv1,
    float2 fn_prev)
{
    const unsigned FULL = 0xffffffffu;
    const float* hp = h + base + (js + 5) * NX + ip;
    const float* up = u + base + (js + 2) * NX + ip;
    const float* vp = v + base + (js + 2) * NX + ip;
    float*       op = out + base + js * NX + ip;

    #pragma unroll 8
    for (int jj = 0; jj < JSTRIP; jj++) {
        const int j = js + jj;
        // ---- prefetches: h row j+5, u/v row j+2 (2-iteration distance) ----
        float2 rpN, uvN, vvN;
        if (MODE == 2) {
            rpN = ld2(&h[base + min(j + 5, NY - 1) * NX + ip]);
            int jn = min(j + 2, NY - 1);
            uvN = ld2(&u[base + jn * NX + ip]);
            vvN = ld2(&v[base + jn * NX + ip]);
        } else {
            rpN = ld2(hp); uvN = ld2(up); vvN = ld2(vp);
        }

        // ---- shift rows: r0..r5 = rows j-2..j+3 ----
        r0 = r1; r1 = r2; r2 = r3; r3 = r4; r4 = r5; r5 = rp;
        float2 c = r2;                               // center row j

        // x-stencil neighbors via intra-warp shuffle
        float2 L, R1, R2;
        L.x  = __shfl_up_sync(FULL, c.x, 1);
        L.y  = __shfl_up_sync(FULL, c.y, 1);
        R1.x = __shfl_down_sync(FULL, c.x, 1);
        R1.y = __shfl_down_sync(FULL, c.y, 1);
        R2.x = __shfl_down_sync(FULL, c.x, 2);
        R2.y = __shfl_down_sync(FULL, c.y, 2);

        // edge / cross-warp fixups from smem halo (lanes 0, 30, 31 only)
        const float* hrow = &sH8[jj * 8];
        if (lane == 0)
            L = left_edge ? make_float2(c.x, c.x) : *(const float2*)&hrow[2];
        if (lane == 31) {
            R1 = right_edge ? make_float2(c.y, c.y) : *(const float2*)&hrow[4];
            R2 = right_edge ? make_float2(c.y, c.y) : *(const float2*)&hrow[6];
        } else if (lane == 30) {
            R2 = right_edge ? make_float2(R1.y, R1.y) : *(const float2*)&hrow[4];
        }

        // ---- x faces at (ip, ip+1) ----
        float fx0, fx1;
        {
            float ax[6] = {L.x, L.y, c.x, c.y, R1.x, R1.y};
            float bx[6] = {L.y, c.x, c.y, R1.x, R1.y, R2.x};
            u64_t m2, m1, z0, p1, p2;
            upwind_pack(ax, bx, uv.x >= 0.f, uv.y >= 0.f, m2, m1, z0, p1, p2);
            weno5x2(m2, m1, z0, p1, p2, fx0, fx1);
            fx0 *= uv.x; fx1 *= uv.y;
        }
        float fxm = __shfl_up_sync(FULL, fx1, 1);    // face at ip-1 from left lane
        float halo = sF[jj];
        if (lane == 0) fxm = halo;

        // ---- y faces at row j (rows j-2..j+3 = r0..r5) ----
        float fy0, fy1;
        {
            float ay[6] = {r0.x, r1.x, r2.x, r3.x, r4.x, r5.x};
            float by[6] = {r0.y, r1.y, r2.y, r3.y, r4.y, r5.y};
            u64_t m2, m1, z0, p1, p2;
            upwind_pack(ay, by, vv.x >= 0.f, vv.y >= 0.f, m2, m1, z0, p1, p2);
            weno5x2(m2, m1, z0, p1, p2, fy0, fy1);
            fy0 *= vv.x; fy1 *= vv.y;
        }

        // ---- divergence via pre-masked multipliers (sxs/sys carry -1 and xok) ----
        float sx = sxs, sy = sys;
        if (MODE == 0) { bool jok = (j >= 2);      sx = jok ? sxs : 0.f; sy = jok ? sys : 0.f; }
        if (MODE == 2) { bool jok = (j <= NY - 3); sx = jok ? sxs : 0.f; sy = jok ? sys : 0.f; }
        float o0 = (fx0 - fxm ) * sx + (fy0 - fn_prev.x) * sy;
        float o1 = (fx1 - fx0) * sx + (fy1 - fn_prev.y) * sy;
        __stcs((float2*)op, make_float2(o0, o1));

        // ---- rotate pipelines ----
        fn_prev = make_float2(fy0, fy1);
        rp = rp2; rp2 = rpN;
        uv = uv1; uv1 = uvN;
        vv = vv1; vv1 = vvN;
        hp += NX; up += NX; vp += NX; op += NX;
    }
}

__global__ __launch_bounds__(32 * WARPS, 7)
void adv3d_kernel(const float* __restrict__ h,
                  const float* __restrict__ u,
                  const float* __restrict__ v,
                  float* __restrict__ out) {
    const int k    = blockIdx.z;
    const int lane = threadIdx.x;
    const int w    = threadIdx.y;
    const int i0   = (blockIdx.x * WARPS + w) * 64;
    const int ip   = i0 + 2 * lane;
    const int js   = blockIdx.y * JSTRIP;
    const int base = k * (NY * NX);

    if (k == 0 || k == NZ - 1) {                 // z boundary slabs: zeros
        float* op = out + base + js * NX + ip;
        #pragma unroll 4
        for (int jj = 0; jj < JSTRIP; jj++) {
            __stcs((float2*)op, make_float2(0.f, 0.f));
            op += NX;
        }
        return;
    }

    __shared__ float sHaloF[WARPS][JSTRIP];       // x-halo FLUX at i0-1 per row
    __shared__ __align__(16) float sHaloH[WARPS][JSTRIP][8]; // h halo cols per row

    const bool left_edge  = (i0 == 0);
    const bool right_edge = (i0 == NX - 64);
    const bool xok = !((left_edge && lane == 0) || (right_edge && lane == 31));
    const float sxs = xok ? -SX : 0.f;
    const float sys = xok ? -SY : 0.f;

    // ---- pre-phase A: stage halo h-columns for all 64 rows into smem ----
    {
        const int lcol = max(i0 - 4, 0);
        const int rcol = min(i0 + 64, NX - 4);
        #pragma unroll
        for (int m = 0; m < 2; m++) {
            int rr = 2 * lane + m;
            int row = js + rr;
            float4 lq = __ldg((const float4*)&h[base + row * NX + lcol]);
            float4 rq = __ldg((const float4*)&h[base + row * NX + rcol]);
            *(float4*)&sHaloH[w][rr][0] = lq;
            *(float4*)&sHaloH[w][rr][4] = rq;
        }
    }

    // ---- pre-phase B: x-halo faces at x = i0-1 for all 64 rows (one packed eval/lane) ----
    {
        int ra = js + 2 * lane, rb = ra + 1;
        float a[6], b[6];
        #pragma unroll
        for (int m = 0; m < 6; m++) {
            int xi = min(max(i0 - 3 + m, 0), NX - 1);
            a[m] = __ldg(&h[base + ra * NX + xi]);
            b[m] = __ldg(&h[base + rb * NX + xi]);
        }
        int xh = max(i0 - 1, 0);
        float ua = __ldg(&u[base + ra * NX + xh]);
        float ub = __ldg(&u[base + rb * NX + xh]);
        u64_t m2, m1, z0, p1, p2;
        upwind_pack(a, b, ua >= 0.f, ub >= 0.f, m2, m1, z0, p1, p2);
        float f0, f1;
        weno5x2(m2, m1, z0, p1, p2, f0, f1);
        sHaloF[w][2 * lane]     = f0 * ua;
        sHaloF[w][2 * lane + 1] = f1 * ub;
    }
    __syncwarp();

    // ---- rolling h rows: r0..r5 = rows js-3..js+2; rp, rp2 = rows js+3, js+4 ----
    float2 r0, r1, r2, r3, r4, r5, rp, rp2;
    {
        #define LOADROW(m) ld2(&h[base + min(max(js - 3 + (m), 0), NY - 1) * NX + ip])
        r0 = LOADROW(0); r1 = LOADROW(1); r2 = LOADROW(2);
        r3 = LOADROW(3); r4 = LOADROW(4); r5 = LOADROW(5);
        rp = LOADROW(6); rp2 = LOADROW(7);
        #undef LOADROW
    }
    // u/v depth-2 pipeline: uv = row js, uv1 = row js+1
    float2 uv  = ld2(&u[base + js * NX + ip]);
    float2 vv  = ld2(&v[base + js * NX + ip]);
    float2 uv1 = ld2(&u[base + min(js + 1, NY - 1) * NX + ip]);
    float2 vv1 = ld2(&v[base + min(js + 1, NY - 1) * NX + ip]);

    // fn_prev: y-face at row js-1 (stencil rows js-3..js+2 = r0..r5)
    float2 fn_prev;
    {
        float2 vh = ld2(&v[base + max(js - 1, 0) * NX + ip]);
        float ay[6] = {r0.x, r1.x, r2.x, r3.x, r4.x, r5.x};
        float by[6] = {r0.y, r1.y, r2.y, r3.y, r4.y, r5.y};
        u64_t m2, m1, z0, p1, p2;
        upwind_pack(ay, by, vh.x >= 0.f, vh.y >= 0.f, m2, m1, z0, p1, p2);
        float f0, f1;
        weno5x2(m2, m1, z0, p1, p2, f0, f1);
        fn_prev = make_float2(f0 * vh.x, f1 * vh.y);
    }

    if (js == 0)
        strip_loop<0>(h, u, v, out, base, ip, js, lane, sxs, sys, left_edge, right_edge,
                      &sHaloF[w][0], &sHaloH[w][0][0],
                      r0, r1, r2, r3, r4, r5, rp, rp2, uv, uv1, vv, vv1, fn_prev);
    else if (js == NY - JSTRIP)
        strip_loop<2>(h, u, v, out, base, ip, js, lane, sxs, sys, left_edge, right_edge,
                      &sHaloF[w][0], &sHaloH[w][0][0],
                      r0, r1, r2, r3, r4, r5, rp, rp2, uv, uv1, vv, vv1, fn_prev);
    else
        strip_loop<1>(h, u, v, out, base, ip, js, lane, sxs, sys, left_edge, right_edge,
                      &sHaloF[w][0], &sHaloH[w][0][0],
                      r0, r1, r2, r3, r4, r5, rp, rp2, uv, uv1, vv, vv1, fn_prev);
}

extern "C" void kernel_launch(void* const* d_in, const int* in_sizes, int n_in,
                              void* d_out, int out_size) {
    const float* h = (const float*)d_in[0];
    const float* u = (const float*)d_in[1];
    const float* v = (const float*)d_in[2];
    float* out = (float*)d_out;

    dim3 block(32, WARPS, 1);
    dim3 grid(NX / (64 * WARPS), NY / JSTRIP, NZ);
    adv3d_kernel<<<grid, block>>>(h, u, v, out);
}